// round 14
// baseline (speedup 1.0000x reference)
#include <cuda_runtime.h>
#include <cuda_fp16.h>

#define BATCH 8
#define LEN   2048
#define EMB   512
#define NQ    8
#define IT    16     // i-rows per attn block
#define JPT   4      // j-columns per thread
#define THR   512    // threads per block (both roles)

#define ROT_BLOCKS    512          // 32 rows each -> 16384 rows
#define ATT_BLOCKS    (BATCH * (LEN / IT))   // 1024
#define ROT_PER_BATCH 64           // rot blocks per batch (2048/32)

// dynamic smem for the tanh buffer: THR*IT*8 bytes = 64 KB
#define SMEM_TH_BYTES (THR * IT * 8)

// scratch for rot = x @ rotation : (8, 2048, 8) fp32 = 512 KB (L2-resident)
__device__ float g_rot[BATCH * LEN * NQ];
__device__ int   g_cnt[BATCH];     // per-batch rot completion counters

__device__ __forceinline__ float tanh_fast(float x) {
    float y;
    asm("tanh.approx.f32 %0, %1;" : "=f"(y) : "f"(x));
    return y;
}
__device__ __forceinline__ unsigned int h2_to_u(__half2 h) {
    return *reinterpret_cast<unsigned int*>(&h);
}
__device__ __forceinline__ __half2 u_to_h2(unsigned int u) {
    return *reinterpret_cast<__half2*>(&u);
}

// swap-butterfly reduce of 8 per-row partials within a warp.
// After: every lane holds the full-warp sum for row (lane & 7).
__device__ __forceinline__ void butterfly8(float a[8], int lane) {
#pragma unroll
    for (int off = 4; off >= 1; off >>= 1) {
#pragma unroll
        for (int t = 0; t < 4; t++) {
            if (t < off) {
                const bool hi = (lane & off) != 0;
                const float give = hi ? a[t] : a[t + off];
                const float keep = hi ? a[t + off] : a[t];
                a[t] = keep + __shfl_xor_sync(0xffffffffu, give, off);
            }
        }
    }
    a[0] += __shfl_xor_sync(0xffffffffu, a[0], 8);
    a[0] += __shfl_xor_sync(0xffffffffu, a[0], 16);
}

// reset the completion counters (graph-replay-safe)
__global__ void reset_kernel()
{
    if (threadIdx.x < BATCH) g_cnt[threadIdx.x] = 0;
}

// ---------------------------------------------------------------------------
// Fused kernel. In-order block dispatch guarantees progress:
//   bids [0, 512):      rot role — no waits; 32 rows/block (16 warps x 2 rows),
//                       8 LDG.128 up-front, swap-butterfly, signal g_cnt[batch].
//   bids [512, 1536):   attn role — spin until its batch's 64 rot blocks done
//                       (all have smaller bids => already dispatched => finish),
//                       then run the R10 attn block unchanged.
// ---------------------------------------------------------------------------
__global__ __launch_bounds__(THR, 2) void fused_kernel(const float* __restrict__ x,
                                                       const float* __restrict__ rotation,
                                                       float* __restrict__ out)
{
    extern __shared__ uint2 s_th[];          // 64 KB (attn role)
    __shared__ float4 srotT4[NQ][EMB / 4];   // 16 KB  (rot role)
    __shared__ float s_q[IT * NQ];
    __shared__ float s_part[IT][16];
    __shared__ float s_h[IT];

    const int bid  = blockIdx.x;
    const int tid  = threadIdx.x;
    const int warp = tid >> 5;
    const int lane = tid & 31;

    if (bid < ROT_BLOCKS) {
        // ------------------------- rot role -------------------------
        float* srot = reinterpret_cast<float*>(srotT4);
        for (int idx = tid; idx < EMB * NQ; idx += THR) {
            int e = idx >> 3;
            int q = idx & 7;
            srot[q * EMB + e] = rotation[idx];
        }
        __syncthreads();

        const int row0 = bid * 32 + warp * 2;   // 2 rows per warp

        // all 8 loads up-front (2 rows x 4 chunks), MLP = 8
        float4 xv[2][4];
#pragma unroll
        for (int r = 0; r < 2; r++)
#pragma unroll
            for (int k = 0; k < 4; k++)
                xv[r][k] = reinterpret_cast<const float4*>(
                    x + (size_t)(row0 + r) * EMB)[k * 32 + lane];

        float a[16];   // a[o], o = r*8+q
#pragma unroll
        for (int o = 0; o < 16; o++) a[o] = 0.0f;

#pragma unroll
        for (int k = 0; k < 4; k++) {
#pragma unroll
            for (int q = 0; q < NQ; q++) {
                const float4 rq = srotT4[q][k * 32 + lane];
#pragma unroll
                for (int r = 0; r < 2; r++) {
                    float& acc = a[r * 8 + q];
                    acc = fmaf(xv[r][k].x, rq.x, acc);
                    acc = fmaf(xv[r][k].y, rq.y, acc);
                    acc = fmaf(xv[r][k].z, rq.z, acc);
                    acc = fmaf(xv[r][k].w, rq.w, acc);
                }
            }
        }

        // swap-butterfly: stages 8,4,2,1 then group-merge; lane l (<16) holds
        // the fully reduced element (row = l>>3, q = l&7).
#pragma unroll
        for (int off = 8; off >= 1; off >>= 1) {
#pragma unroll
            for (int t = 0; t < 8; t++) {
                if (t < off) {
                    const bool hi = (lane & off) != 0;
                    const float give = hi ? a[t] : a[t + off];
                    const float keep = hi ? a[t + off] : a[t];
                    a[t] = keep + __shfl_xor_sync(0xffffffffu, give, off);
                }
            }
        }
        a[0] += __shfl_xor_sync(0xffffffffu, a[0], 16);

        if (lane < 16)
            g_rot[(size_t)row0 * NQ + lane] = a[0];

        // signal: all stores done -> fence -> count this block for its batch
        __syncthreads();
        __threadfence();
        if (tid == 0)
            atomicAdd(&g_cnt[bid / ROT_PER_BATCH], 1);
        return;
    }

    // ------------------------- attn role -------------------------
    const int aid = bid - ROT_BLOCKS;
    const int b   = aid >> 7;            // 128 i-tiles per batch
    const int i0  = (aid & 127) * IT;

    // wait for this batch's rot blocks (all have smaller bids)
    if (tid == 0) {
        while (*(volatile int*)&g_cnt[b] < ROT_PER_BATCH)
            __nanosleep(64);
    }
    __syncthreads();
    __threadfence();   // acquire: order g_rot reads after counter observation

    if (tid < IT * NQ)
        s_q[tid] = 0.5f * g_rot[((size_t)b * LEN + i0) * NQ + tid];

    // this thread's 4 j-rows (128B contiguous): 8 x LDG.128, MLP = 8
    const float4* rj = reinterpret_cast<const float4*>(
        &g_rot[((size_t)b * LEN + tid * JPT) * NQ]);
    float4 v0[JPT], v1[JPT];
#pragma unroll
    for (int r = 0; r < JPT; r++) {
        v0[r] = __ldg(rj + r * 2 + 0);
        v1[r] = __ldg(rj + r * 2 + 1);
    }

    __syncthreads();

    const float4* sq4 = reinterpret_cast<const float4*>(s_q);
    float a[8];

#pragma unroll
    for (int half = 0; half < 2; half++) {
#pragma unroll
        for (int u = 0; u < 8; u++) {
            const int i = half * 8 + u;
            const float4 q0 = sq4[i * 2 + 0];   // broadcast LDS.128
            const float4 q1 = sq4[i * 2 + 1];
            float t[JPT];
#pragma unroll
            for (int r = 0; r < JPT; r++) {
                float s0 = v0[r].x * q0.x;
                float s1 = v1[r].x * q1.x;
                s0 = fmaf(v0[r].y, q0.y, s0);
                s1 = fmaf(v1[r].y, q1.y, s1);
                s0 = fmaf(v0[r].z, q0.z, s0);
                s1 = fmaf(v1[r].z, q1.z, s1);
                s0 = fmaf(v0[r].w, q0.w, s0);
                s1 = fmaf(v1[r].w, q1.w, s1);
                t[r] = tanh_fast(s0 + s1);
            }
            a[u] = (t[0] + t[1]) + (t[2] + t[3]);
            uint2 u2;
            u2.x = h2_to_u(__floats2half2_rn(t[0], t[1]));
            u2.y = h2_to_u(__floats2half2_rn(t[2], t[3]));
            s_th[i * THR + tid] = u2;           // STS.64, conflict-free
        }
        butterfly8(a, lane);
        if (lane < 8)
            s_part[half * 8 + lane][warp] = a[0];
    }

    __syncthreads();

    // second level: warp w (16 warps) reduces row w's 16 warp-partials
    {
        float p = (lane < 16) ? s_part[warp][lane] : 0.0f;
#pragma unroll
        for (int off = 8; off >= 1; off >>= 1)
            p += __shfl_xor_sync(0xffffffffu, p, off);
        if (lane == 0)
            s_h[warp] = __fdividef(0.5f, fmaf(0.5f, p, 1024.0f));
    }
    __syncthreads();

    float4* obase = reinterpret_cast<float4*>(
        out + ((size_t)(b * LEN + i0)) * LEN) + tid;
#pragma unroll
    for (int i = 0; i < IT; i++) {
        const float h = s_h[i];
        const uint2 u2 = s_th[i * THR + tid];   // LDS.64, conflict-free
        const float2 lo = __half22float2(u_to_h2(u2.x));
        const float2 hi = __half22float2(u_to_h2(u2.y));
        float4 o;
        o.x = fmaf(lo.x, h, h);
        o.y = fmaf(lo.y, h, h);
        o.z = fmaf(hi.x, h, h);
        o.w = fmaf(hi.y, h, h);
        __stcs(obase, o);                       // evict-first streaming STG.128
        obase += LEN / 4;
    }
}

extern "C" void kernel_launch(void* const* d_in, const int* in_sizes, int n_in,
                              void* d_out, int out_size)
{
    const float* x        = (const float*)d_in[0];   // (8, 2048, 512)
    const float* rotation = (const float*)d_in[1];   // (512, 8)
    float* out = (float*)d_out;                      // (8, 2048, 2048)

    static int init = 0;
    if (!init) {
        cudaFuncSetAttribute(fused_kernel,
                             cudaFuncAttributeMaxDynamicSharedMemorySize,
                             SMEM_TH_BYTES);
        init = 1;
    }

    reset_kernel<<<1, 32>>>();
    fused_kernel<<<ROT_BLOCKS + ATT_BLOCKS, THR, SMEM_TH_BYTES>>>(x, rotation, out);
}

// round 15
// speedup vs baseline: 1.1137x; 1.1137x over previous
#include <cuda_runtime.h>
#include <cuda_fp16.h>

#define BATCH 8
#define LEN   2048
#define EMB   512
#define NQ    8
#define IT    16     // i-rows per attn block
#define JPT   4      // j-columns per thread
#define THR   512    // attn block size

// dynamic smem for the tanh buffer: THR*IT*8 bytes = 64 KB
#define SMEM_TH_BYTES (THR * IT * 8)

// scratch for rot = x @ rotation : (8, 2048, 8) fp32 = 512 KB (L2-resident)
__device__ float g_rot[BATCH * LEN * NQ];

__device__ __forceinline__ float tanh_fast(float x) {
    float y;
    asm("tanh.approx.f32 %0, %1;" : "=f"(y) : "f"(x));
    return y;
}
__device__ __forceinline__ unsigned int h2_to_u(__half2 h) {
    return *reinterpret_cast<unsigned int*>(&h);
}
__device__ __forceinline__ __half2 u_to_h2(unsigned int u) {
    return *reinterpret_cast<__half2*>(&u);
}

// ---------------------------------------------------------------------------
// Kernel 1: rot[b,l,q] = sum_e x[b,l,e] * rotation[e,q]   (R10 exact form)
// 512 blocks x 256 threads. Each warp computes 4 rows; 16 LDG.128 up-front
// (MLP=16). Full 5-stage swap-butterfly -> lane l holds element (l>>3, l&7):
// contiguous 128B STG per warp.
// ---------------------------------------------------------------------------
__global__ __launch_bounds__(256) void rot_kernel(const float* __restrict__ x,
                                                  const float* __restrict__ rotation)
{
    __shared__ float4 srotT4[NQ][EMB / 4];   // transposed rotation, 16 KB
    const int tid = threadIdx.x;

    float* srot = reinterpret_cast<float*>(srotT4);
    for (int idx = tid; idx < EMB * NQ; idx += 256) {
        int e = idx >> 3;
        int q = idx & 7;
        srot[q * EMB + e] = rotation[idx];
    }
    __syncthreads();

    const int warp = tid >> 5;
    const int lane = tid & 31;
    const int row0 = (blockIdx.x * 8 + warp) * 4;   // 4 rows per warp

    // issue all 16 global loads first (4 rows x 4 chunks), MLP = 16
    float4 xv[4][4];
#pragma unroll
    for (int r = 0; r < 4; r++)
#pragma unroll
        for (int k = 0; k < 4; k++)
            xv[r][k] = reinterpret_cast<const float4*>(
                x + (size_t)(row0 + r) * EMB)[k * 32 + lane];

    float a[32];   // a[o], o = r*8+q
#pragma unroll
    for (int o = 0; o < 32; o++) a[o] = 0.0f;

#pragma unroll
    for (int k = 0; k < 4; k++) {
#pragma unroll
        for (int q = 0; q < NQ; q++) {
            const float4 rq = srotT4[q][k * 32 + lane];
#pragma unroll
            for (int r = 0; r < 4; r++) {
                float& acc = a[r * 8 + q];
                acc = fmaf(xv[r][k].x, rq.x, acc);
                acc = fmaf(xv[r][k].y, rq.y, acc);
                acc = fmaf(xv[r][k].z, rq.z, acc);
                acc = fmaf(xv[r][k].w, rq.w, acc);
            }
        }
    }

    // full swap-butterfly: after stages 16,8,4,2,1 lane l holds a[l] reduced
#pragma unroll
    for (int off = 16; off >= 1; off >>= 1) {
#pragma unroll
        for (int t = 0; t < 16; t++) {
            if (t < off) {
                const bool hi = (lane & off) != 0;
                const float give = hi ? a[t] : a[t + off];
                const float keep = hi ? a[t + off] : a[t];
                a[t] = keep + __shfl_xor_sync(0xffffffffu, give, off);
            }
        }
    }

    g_rot[(size_t)row0 * NQ + lane] = a[0];
}

// swap-butterfly reduce of 8 per-row partials within a warp.
// After: every lane holds the full-warp sum for row (lane & 7).
__device__ __forceinline__ void butterfly8(float a[8], int lane) {
#pragma unroll
    for (int off = 4; off >= 1; off >>= 1) {
#pragma unroll
        for (int t = 0; t < 4; t++) {
            if (t < off) {
                const bool hi = (lane & off) != 0;
                const float give = hi ? a[t] : a[t + off];
                const float keep = hi ? a[t + off] : a[t];
                a[t] = keep + __shfl_xor_sync(0xffffffffu, give, off);
            }
        }
    }
    a[0] += __shfl_xor_sync(0xffffffffu, a[0], 8);
    a[0] += __shfl_xor_sync(0xffffffffu, a[0], 16);
}

// ---------------------------------------------------------------------------
// Kernel 2: scores[b,i,j] = sigmoid(rot_i . rot_j) / row_sum
//   sigmoid(s) = 0.5 + 0.5*tanh(0.5*s)   (0.5 folded into qi)
//   row_sum    = 1024 + 0.5*sum_j tanh   ->  out = fmaf(t, h, h), h = 0.5/row_sum
// Block = 512 threads, IT=16, JPT=4, grid (128, 8), 2 blocks/SM.
// PHASE-OVERLAPPED: rows 0-7 computed+reduced first; their output stores are
// interleaved into the compute loop of rows 8-15 (s_th is same-thread data,
// so only s_h needs barriers) -> MIO store work overlaps FMA/MUFU compute.
// ---------------------------------------------------------------------------
__global__ __launch_bounds__(THR, 2) void attn_kernel(float* __restrict__ out)
{
    extern __shared__ uint2 s_th[];     // [i*THR + tid]  (64 KB)
    __shared__ float s_q[IT * NQ];      // 0.5 * qi rows
    __shared__ float s_part[IT][16];
    __shared__ float s_h[IT];

    const int b    = blockIdx.y;
    const int i0   = blockIdx.x * IT;
    const int tid  = threadIdx.x;
    const int warp = tid >> 5;
    const int lane = tid & 31;

    if (tid < IT * NQ)
        s_q[tid] = 0.5f * g_rot[((size_t)b * LEN + i0) * NQ + tid];

    // this thread's 4 j-rows (128B contiguous): 8 x LDG.128, MLP = 8
    const float4* rj = reinterpret_cast<const float4*>(
        &g_rot[((size_t)b * LEN + tid * JPT) * NQ]);
    float4 v0[JPT], v1[JPT];
#pragma unroll
    for (int r = 0; r < JPT; r++) {
        v0[r] = __ldg(rj + r * 2 + 0);
        v1[r] = __ldg(rj + r * 2 + 1);
    }

    __syncthreads();

    const float4* sq4 = reinterpret_cast<const float4*>(s_q);
    float4* const obase0 = reinterpret_cast<float4*>(
        out + ((size_t)(b * LEN + i0)) * LEN) + tid;
    float a[8];

    // ---- phase A: compute rows 0..7 ----
#pragma unroll
    for (int u = 0; u < 8; u++) {
        const float4 q0 = sq4[u * 2 + 0];
        const float4 q1 = sq4[u * 2 + 1];
        float t[JPT];
#pragma unroll
        for (int r = 0; r < JPT; r++) {
            float s0 = v0[r].x * q0.x;
            float s1 = v1[r].x * q1.x;
            s0 = fmaf(v0[r].y, q0.y, s0);
            s1 = fmaf(v1[r].y, q1.y, s1);
            s0 = fmaf(v0[r].z, q0.z, s0);
            s1 = fmaf(v1[r].z, q1.z, s1);
            s0 = fmaf(v0[r].w, q0.w, s0);
            s1 = fmaf(v1[r].w, q1.w, s1);
            t[r] = tanh_fast(s0 + s1);
        }
        a[u] = (t[0] + t[1]) + (t[2] + t[3]);
        uint2 u2;
        u2.x = h2_to_u(__floats2half2_rn(t[0], t[1]));
        u2.y = h2_to_u(__floats2half2_rn(t[2], t[3]));
        s_th[u * THR + tid] = u2;
    }
    butterfly8(a, lane);
    if (lane < 8)
        s_part[lane][warp] = a[0];

    __syncthreads();

    // early second-level reduction for rows 0..7 (warps 0..7)
    if (warp < 8) {
        float p = (lane < 16) ? s_part[warp][lane] : 0.0f;
#pragma unroll
        for (int off = 8; off >= 1; off >>= 1)
            p += __shfl_xor_sync(0xffffffffu, p, off);
        if (lane == 0)
            s_h[warp] = __fdividef(0.5f, fmaf(0.5f, p, 1024.0f));
    }
    __syncthreads();

    // ---- phase B: compute rows 8..15 INTERLEAVED with stores of rows 0..7 ----
#pragma unroll
    for (int u = 0; u < 8; u++) {
        const int i = 8 + u;
        const float4 q0 = sq4[i * 2 + 0];
        const float4 q1 = sq4[i * 2 + 1];
        float t[JPT];
#pragma unroll
        for (int r = 0; r < JPT; r++) {
            float s0 = v0[r].x * q0.x;
            float s1 = v1[r].x * q1.x;
            s0 = fmaf(v0[r].y, q0.y, s0);
            s1 = fmaf(v1[r].y, q1.y, s1);
            s0 = fmaf(v0[r].z, q0.z, s0);
            s1 = fmaf(v1[r].z, q1.z, s1);
            s0 = fmaf(v0[r].w, q0.w, s0);
            s1 = fmaf(v1[r].w, q1.w, s1);
            t[r] = tanh_fast(s0 + s1);
        }
        a[u] = (t[0] + t[1]) + (t[2] + t[3]);
        uint2 u2;
        u2.x = h2_to_u(__floats2half2_rn(t[0], t[1]));
        u2.y = h2_to_u(__floats2half2_rn(t[2], t[3]));
        s_th[i * THR + tid] = u2;

        // store output row u (phase-A row): same-thread s_th data + ready s_h
        {
            const float h = s_h[u];
            const uint2 w2 = s_th[u * THR + tid];
            const float2 lo = __half22float2(u_to_h2(w2.x));
            const float2 hi = __half22float2(u_to_h2(w2.y));
            float4 o;
            o.x = fmaf(lo.x, h, h);
            o.y = fmaf(lo.y, h, h);
            o.z = fmaf(hi.x, h, h);
            o.w = fmaf(hi.y, h, h);
            __stcs(obase0 + (size_t)u * (LEN / 4), o);
        }
    }
    butterfly8(a, lane);
    if (lane < 8)
        s_part[8 + lane][warp] = a[0];

    __syncthreads();

    // second-level reduction for rows 8..15 (warps 8..15)
    if (warp >= 8) {
        float p = (lane < 16) ? s_part[warp][lane] : 0.0f;
#pragma unroll
        for (int off = 8; off >= 1; off >>= 1)
            p += __shfl_xor_sync(0xffffffffu, p, off);
        if (lane == 0)
            s_h[warp] = __fdividef(0.5f, fmaf(0.5f, p, 1024.0f));
    }
    __syncthreads();

    // ---- tail: store rows 8..15 ----
#pragma unroll
    for (int u = 0; u < 8; u++) {
        const int i = 8 + u;
        const float h = s_h[i];
        const uint2 w2 = s_th[i * THR + tid];
        const float2 lo = __half22float2(u_to_h2(w2.x));
        const float2 hi = __half22float2(u_to_h2(w2.y));
        float4 o;
        o.x = fmaf(lo.x, h, h);
        o.y = fmaf(lo.y, h, h);
        o.z = fmaf(hi.x, h, h);
        o.w = fmaf(hi.y, h, h);
        __stcs(obase0 + (size_t)i * (LEN / 4), o);
    }
}

extern "C" void kernel_launch(void* const* d_in, const int* in_sizes, int n_in,
                              void* d_out, int out_size)
{
    const float* x        = (const float*)d_in[0];   // (8, 2048, 512)
    const float* rotation = (const float*)d_in[1];   // (512, 8)
    float* out = (float*)d_out;                      // (8, 2048, 2048)

    static int init = 0;
    if (!init) {
        cudaFuncSetAttribute(attn_kernel,
                             cudaFuncAttributeMaxDynamicSharedMemorySize,
                             SMEM_TH_BYTES);
        init = 1;
    }

    rot_kernel<<<512, 256>>>(x, rotation);

    dim3 grid(LEN / IT, BATCH);                      // (128, 8)
    attn_kernel<<<grid, THR, SMEM_TH_BYTES>>>(out);
}

// round 16
// speedup vs baseline: 1.1157x; 1.0018x over previous
#include <cuda_runtime.h>
#include <cuda_fp16.h>

#define BATCH 8
#define LEN   2048
#define EMB   512
#define NQ    8
#define IT    16     // i-rows per attn block
#define JPT   4      // j-columns per thread
#define THR   512    // attn block size

// scratch for rot = x @ rotation : (8, 2048, 8) fp32 = 512 KB (L2-resident)
__device__ float g_rot[BATCH * LEN * NQ];

__device__ __forceinline__ float tanh_fast(float x) {
    float y;
    asm("tanh.approx.f32 %0, %1;" : "=f"(y) : "f"(x));
    return y;
}
__device__ __forceinline__ unsigned int h2_to_u(__half2 h) {
    return *reinterpret_cast<unsigned int*>(&h);
}
__device__ __forceinline__ __half2 u_to_h2(unsigned int u) {
    return *reinterpret_cast<__half2*>(&u);
}

// ---------------------------------------------------------------------------
// Kernel 1: rot[b,l,q] = sum_e x[b,l,e] * rotation[e,q]   (R10 exact form)
// 512 blocks x 256 threads. Each warp computes 4 rows; 16 LDG.128 up-front
// (MLP=16). Full 5-stage swap-butterfly -> lane l holds element (l>>3, l&7):
// contiguous 128B STG per warp.
// ---------------------------------------------------------------------------
__global__ __launch_bounds__(256) void rot_kernel(const float* __restrict__ x,
                                                  const float* __restrict__ rotation)
{
    __shared__ float4 srotT4[NQ][EMB / 4];   // transposed rotation, 16 KB
    const int tid = threadIdx.x;

    float* srot = reinterpret_cast<float*>(srotT4);
    for (int idx = tid; idx < EMB * NQ; idx += 256) {
        int e = idx >> 3;
        int q = idx & 7;
        srot[q * EMB + e] = rotation[idx];
    }
    __syncthreads();

    const int warp = tid >> 5;
    const int lane = tid & 31;
    const int row0 = (blockIdx.x * 8 + warp) * 4;   // 4 rows per warp

    // issue all 16 global loads first (4 rows x 4 chunks), MLP = 16
    float4 xv[4][4];
#pragma unroll
    for (int r = 0; r < 4; r++)
#pragma unroll
        for (int k = 0; k < 4; k++)
            xv[r][k] = reinterpret_cast<const float4*>(
                x + (size_t)(row0 + r) * EMB)[k * 32 + lane];

    float a[32];   // a[o], o = r*8+q
#pragma unroll
    for (int o = 0; o < 32; o++) a[o] = 0.0f;

#pragma unroll
    for (int k = 0; k < 4; k++) {
#pragma unroll
        for (int q = 0; q < NQ; q++) {
            const float4 rq = srotT4[q][k * 32 + lane];
#pragma unroll
            for (int r = 0; r < 4; r++) {
                float& acc = a[r * 8 + q];
                acc = fmaf(xv[r][k].x, rq.x, acc);
                acc = fmaf(xv[r][k].y, rq.y, acc);
                acc = fmaf(xv[r][k].z, rq.z, acc);
                acc = fmaf(xv[r][k].w, rq.w, acc);
            }
        }
    }

    // full swap-butterfly: after stages 16,8,4,2,1 lane l holds a[l] reduced
#pragma unroll
    for (int off = 16; off >= 1; off >>= 1) {
#pragma unroll
        for (int t = 0; t < 16; t++) {
            if (t < off) {
                const bool hi = (lane & off) != 0;
                const float give = hi ? a[t] : a[t + off];
                const float keep = hi ? a[t + off] : a[t];
                a[t] = keep + __shfl_xor_sync(0xffffffffu, give, off);
            }
        }
    }

    g_rot[(size_t)row0 * NQ + lane] = a[0];
}

// swap-butterfly reduce of 4 per-row partials within a warp.
// After: every lane holds the full-warp sum for row (lane & 3).
__device__ __forceinline__ void butterfly4(float a[4], int lane) {
#pragma unroll
    for (int off = 2; off >= 1; off >>= 1) {
#pragma unroll
        for (int t = 0; t < 2; t++) {
            if (t < off) {
                const bool hi = (lane & off) != 0;
                const float give = hi ? a[t] : a[t + off];
                const float keep = hi ? a[t + off] : a[t];
                a[t] = keep + __shfl_xor_sync(0xffffffffu, give, off);
            }
        }
    }
    a[0] += __shfl_xor_sync(0xffffffffu, a[0], 4);
    a[0] += __shfl_xor_sync(0xffffffffu, a[0], 8);
    a[0] += __shfl_xor_sync(0xffffffffu, a[0], 16);
}

// ---------------------------------------------------------------------------
// Kernel 2: scores[b,i,j] = sigmoid(rot_i . rot_j) / row_sum
//   sigmoid(s) = 0.5 + 0.5*tanh(0.5*s)   (0.5 folded into qi)
//   row_sum    = 1024 + 0.5*sum_j tanh   ->  out = fmaf(t, h, h), h = 0.5/row_sum
// Block = 512 threads, IT=16, JPT=4, grid (128, 8), 2 blocks/SM.
// 4-group software pipeline: group g's tanh values stay in 8 carry registers
// until group g+1, whose compute loop interleaves their stores — NO smem
// tanh buffer at all (removes 16 STS.64 + 16 LDS.64 per thread and 64 KB
// of dynamic smem). 12/16 output stores overlap compute.
// ---------------------------------------------------------------------------
__global__ __launch_bounds__(THR, 2) void attn_kernel(float* __restrict__ out)
{
    __shared__ float s_q[IT * NQ];      // 0.5 * qi rows
    __shared__ float s_part[IT][16];
    __shared__ float s_h[IT];

    const int b    = blockIdx.y;
    const int i0   = blockIdx.x * IT;
    const int tid  = threadIdx.x;
    const int warp = tid >> 5;
    const int lane = tid & 31;

    if (tid < IT * NQ)
        s_q[tid] = 0.5f * g_rot[((size_t)b * LEN + i0) * NQ + tid];

    // this thread's 4 j-rows (128B contiguous): 8 x LDG.128, MLP = 8
    const float4* rj = reinterpret_cast<const float4*>(
        &g_rot[((size_t)b * LEN + tid * JPT) * NQ]);
    float4 v0[JPT], v1[JPT];
#pragma unroll
    for (int r = 0; r < JPT; r++) {
        v0[r] = __ldg(rj + r * 2 + 0);
        v1[r] = __ldg(rj + r * 2 + 1);
    }

    __syncthreads();

    const float4* sq4 = reinterpret_cast<const float4*>(s_q);
    float4* const obase0 = reinterpret_cast<float4*>(
        out + ((size_t)(b * LEN + i0)) * LEN) + tid;

    uint2 carry[4];   // previous group's tanh values (4 rows x 4 half)

#pragma unroll
    for (int g = 0; g < 4; g++) {
        float a[4];
        uint2 fresh[4];
#pragma unroll
        for (int u = 0; u < 4; u++) {
            const int i = g * 4 + u;
            const float4 q0 = sq4[i * 2 + 0];   // broadcast LDS.128
            const float4 q1 = sq4[i * 2 + 1];
            float t[JPT];
#pragma unroll
            for (int r = 0; r < JPT; r++) {
                float s0 = v0[r].x * q0.x;
                float s1 = v1[r].x * q1.x;
                s0 = fmaf(v0[r].y, q0.y, s0);
                s1 = fmaf(v1[r].y, q1.y, s1);
                s0 = fmaf(v0[r].z, q0.z, s0);
                s1 = fmaf(v1[r].z, q1.z, s1);
                s0 = fmaf(v0[r].w, q0.w, s0);
                s1 = fmaf(v1[r].w, q1.w, s1);
                t[r] = tanh_fast(s0 + s1);
            }
            a[u] = (t[0] + t[1]) + (t[2] + t[3]);
            fresh[u].x = h2_to_u(__floats2half2_rn(t[0], t[1]));
            fresh[u].y = h2_to_u(__floats2half2_rn(t[2], t[3]));

            // interleaved store of previous group's row (g-1)*4+u
            if (g > 0) {
                const int ip = (g - 1) * 4 + u;
                const float h = s_h[ip];
                const float2 lo = __half22float2(u_to_h2(carry[u].x));
                const float2 hi = __half22float2(u_to_h2(carry[u].y));
                float4 o;
                o.x = fmaf(lo.x, h, h);
                o.y = fmaf(lo.y, h, h);
                o.z = fmaf(hi.x, h, h);
                o.w = fmaf(hi.y, h, h);
                __stcs(obase0 + (size_t)ip * (LEN / 4), o);
            }
        }

        // first-level reduce of this group's 4 row-partials
        butterfly4(a, lane);
        if (lane < 4)
            s_part[g * 4 + lane][warp] = a[0];
        __syncthreads();

        // second-level: warps g*4 .. g*4+3 reduce their row's 16 partials
        if ((warp >> 2) == g) {
            float p = (lane < 16) ? s_part[warp][lane] : 0.0f;
#pragma unroll
            for (int off = 8; off >= 1; off >>= 1)
                p += __shfl_xor_sync(0xffffffffu, p, off);
            if (lane == 0)
                s_h[warp] = __fdividef(0.5f, fmaf(0.5f, p, 1024.0f));
        }
        __syncthreads();

        // rotate carry (registers; groups fully unrolled so this is renaming)
#pragma unroll
        for (int u = 0; u < 4; u++) carry[u] = fresh[u];
    }

    // tail: store group 3's rows
#pragma unroll
    for (int u = 0; u < 4; u++) {
        const int i = 12 + u;
        const float h = s_h[i];
        const float2 lo = __half22float2(u_to_h2(carry[u].x));
        const float2 hi = __half22float2(u_to_h2(carry[u].y));
        float4 o;
        o.x = fmaf(lo.x, h, h);
        o.y = fmaf(lo.y, h, h);
        o.z = fmaf(hi.x, h, h);
        o.w = fmaf(hi.y, h, h);
        __stcs(obase0 + (size_t)i * (LEN / 4), o);
    }
}

extern "C" void kernel_launch(void* const* d_in, const int* in_sizes, int n_in,
                              void* d_out, int out_size)
{
    const float* x        = (const float*)d_in[0];   // (8, 2048, 512)
    const float* rotation = (const float*)d_in[1];   // (512, 8)
    float* out = (float*)d_out;                      // (8, 2048, 2048)

    rot_kernel<<<512, 256>>>(x, rotation);

    dim3 grid(LEN / IT, BATCH);                      // (128, 8)
    attn_kernel<<<grid, THR>>>(out);
}

// round 17
// speedup vs baseline: 1.2574x; 1.1270x over previous
#include <cuda_runtime.h>
#include <cuda_fp16.h>

#define BATCH 8
#define LEN   2048
#define EMB   512
#define NQ    8
#define IT    32     // i-rows per attn block (buffer-free pipeline makes this cheap)
#define JPT   4      // j-columns per thread
#define THR   512    // attn block size
#define NGRP  (IT / 4)

// scratch for rot = x @ rotation : (8, 2048, 8) fp32 = 512 KB (L2-resident)
__device__ float g_rot[BATCH * LEN * NQ];

__device__ __forceinline__ float tanh_fast(float x) {
    float y;
    asm("tanh.approx.f32 %0, %1;" : "=f"(y) : "f"(x));
    return y;
}
__device__ __forceinline__ unsigned int h2_to_u(__half2 h) {
    return *reinterpret_cast<unsigned int*>(&h);
}
__device__ __forceinline__ __half2 u_to_h2(unsigned int u) {
    return *reinterpret_cast<__half2*>(&u);
}

// ---------------------------------------------------------------------------
// Kernel 1: rot[b,l,q] = sum_e x[b,l,e] * rotation[e,q]   (R10 exact form)
// 512 blocks x 256 threads. Each warp computes 4 rows; 16 LDG.128 up-front
// (MLP=16). Full 5-stage swap-butterfly -> lane l holds element (l>>3, l&7):
// contiguous 128B STG per warp.
// ---------------------------------------------------------------------------
__global__ __launch_bounds__(256) void rot_kernel(const float* __restrict__ x,
                                                  const float* __restrict__ rotation)
{
    __shared__ float4 srotT4[NQ][EMB / 4];   // transposed rotation, 16 KB
    const int tid = threadIdx.x;

    float* srot = reinterpret_cast<float*>(srotT4);
    for (int idx = tid; idx < EMB * NQ; idx += 256) {
        int e = idx >> 3;
        int q = idx & 7;
        srot[q * EMB + e] = rotation[idx];
    }
    __syncthreads();

    const int warp = tid >> 5;
    const int lane = tid & 31;
    const int row0 = (blockIdx.x * 8 + warp) * 4;   // 4 rows per warp

    // issue all 16 global loads first (4 rows x 4 chunks), MLP = 16
    float4 xv[4][4];
#pragma unroll
    for (int r = 0; r < 4; r++)
#pragma unroll
        for (int k = 0; k < 4; k++)
            xv[r][k] = reinterpret_cast<const float4*>(
                x + (size_t)(row0 + r) * EMB)[k * 32 + lane];

    float a[32];   // a[o], o = r*8+q
#pragma unroll
    for (int o = 0; o < 32; o++) a[o] = 0.0f;

#pragma unroll
    for (int k = 0; k < 4; k++) {
#pragma unroll
        for (int q = 0; q < NQ; q++) {
            const float4 rq = srotT4[q][k * 32 + lane];
#pragma unroll
            for (int r = 0; r < 4; r++) {
                float& acc = a[r * 8 + q];
                acc = fmaf(xv[r][k].x, rq.x, acc);
                acc = fmaf(xv[r][k].y, rq.y, acc);
                acc = fmaf(xv[r][k].z, rq.z, acc);
                acc = fmaf(xv[r][k].w, rq.w, acc);
            }
        }
    }

    // full swap-butterfly: after stages 16,8,4,2,1 lane l holds a[l] reduced
#pragma unroll
    for (int off = 16; off >= 1; off >>= 1) {
#pragma unroll
        for (int t = 0; t < 16; t++) {
            if (t < off) {
                const bool hi = (lane & off) != 0;
                const float give = hi ? a[t] : a[t + off];
                const float keep = hi ? a[t + off] : a[t];
                a[t] = keep + __shfl_xor_sync(0xffffffffu, give, off);
            }
        }
    }

    g_rot[(size_t)row0 * NQ + lane] = a[0];
}

// swap-butterfly reduce of 4 per-row partials within a warp.
// After: every lane holds the full-warp sum for row (lane & 3).
__device__ __forceinline__ void butterfly4(float a[4], int lane) {
#pragma unroll
    for (int off = 2; off >= 1; off >>= 1) {
#pragma unroll
        for (int t = 0; t < 2; t++) {
            if (t < off) {
                const bool hi = (lane & off) != 0;
                const float give = hi ? a[t] : a[t + off];
                const float keep = hi ? a[t + off] : a[t];
                a[t] = keep + __shfl_xor_sync(0xffffffffu, give, off);
            }
        }
    }
    a[0] += __shfl_xor_sync(0xffffffffu, a[0], 4);
    a[0] += __shfl_xor_sync(0xffffffffu, a[0], 8);
    a[0] += __shfl_xor_sync(0xffffffffu, a[0], 16);
}

// ---------------------------------------------------------------------------
// Kernel 2: scores[b,i,j] = sigmoid(rot_i . rot_j) / row_sum
//   sigmoid(s) = 0.5 + 0.5*tanh(0.5*s)   (0.5 folded into qi)
//   row_sum    = 1024 + 0.5*sum_j tanh   ->  out = fmaf(t, h, h), h = 0.5/row_sum
// Block = 512 threads, IT=32, JPT=4, grid (64, 8) = 512 blocks, 2 blocks/SM.
// j-rows read ONCE per 32 i-rows (halved L2 read traffic vs IT=16).
// 8-group register pipeline: group g's tanh values live in 8 carry regs until
// group g+1's compute loop interleaves their stores. No smem tanh buffer.
// Second-level row reduction for group g by warps (g&3)*4..+3.
// ---------------------------------------------------------------------------
__global__ __launch_bounds__(THR, 2) void attn_kernel(float* __restrict__ out)
{
    __shared__ float s_q[IT * NQ];      // 0.5 * qi rows (256 floats)
    __shared__ float s_part[IT][16];
    __shared__ float s_h[IT];

    const int b    = blockIdx.y;
    const int i0   = blockIdx.x * IT;
    const int tid  = threadIdx.x;
    const int warp = tid >> 5;
    const int lane = tid & 31;

    if (tid < IT * NQ)
        s_q[tid] = 0.5f * g_rot[((size_t)b * LEN + i0) * NQ + tid];

    // this thread's 4 j-rows (128B contiguous): 8 x LDG.128, MLP = 8
    const float4* rj = reinterpret_cast<const float4*>(
        &g_rot[((size_t)b * LEN + tid * JPT) * NQ]);
    float4 v0[JPT], v1[JPT];
#pragma unroll
    for (int r = 0; r < JPT; r++) {
        v0[r] = __ldg(rj + r * 2 + 0);
        v1[r] = __ldg(rj + r * 2 + 1);
    }

    __syncthreads();

    const float4* sq4 = reinterpret_cast<const float4*>(s_q);
    float4* const obase0 = reinterpret_cast<float4*>(
        out + ((size_t)(b * LEN + i0)) * LEN) + tid;

    uint2 carry[4];   // previous group's tanh values (4 rows x 4 half)

#pragma unroll
    for (int g = 0; g < NGRP; g++) {
        float a[4];
        uint2 fresh[4];
#pragma unroll
        for (int u = 0; u < 4; u++) {
            const int i = g * 4 + u;
            const float4 q0 = sq4[i * 2 + 0];   // broadcast LDS.128
            const float4 q1 = sq4[i * 2 + 1];
            float t[JPT];
#pragma unroll
            for (int r = 0; r < JPT; r++) {
                float s0 = v0[r].x * q0.x;
                float s1 = v1[r].x * q1.x;
                s0 = fmaf(v0[r].y, q0.y, s0);
                s1 = fmaf(v1[r].y, q1.y, s1);
                s0 = fmaf(v0[r].z, q0.z, s0);
                s1 = fmaf(v1[r].z, q1.z, s1);
                s0 = fmaf(v0[r].w, q0.w, s0);
                s1 = fmaf(v1[r].w, q1.w, s1);
                t[r] = tanh_fast(s0 + s1);
            }
            a[u] = (t[0] + t[1]) + (t[2] + t[3]);
            fresh[u].x = h2_to_u(__floats2half2_rn(t[0], t[1]));
            fresh[u].y = h2_to_u(__floats2half2_rn(t[2], t[3]));

            // interleaved store of previous group's row (g-1)*4+u
            if (g > 0) {
                const int ip = (g - 1) * 4 + u;
                const float h = s_h[ip];
                const float2 lo = __half22float2(u_to_h2(carry[u].x));
                const float2 hi = __half22float2(u_to_h2(carry[u].y));
                float4 o;
                o.x = fmaf(lo.x, h, h);
                o.y = fmaf(lo.y, h, h);
                o.z = fmaf(hi.x, h, h);
                o.w = fmaf(hi.y, h, h);
                __stcs(obase0 + (size_t)ip * (LEN / 4), o);
            }
        }

        // first-level reduce of this group's 4 row-partials
        butterfly4(a, lane);
        if (lane < 4)
            s_part[g * 4 + lane][warp] = a[0];
        __syncthreads();

        // second-level: warps (g&3)*4 .. +3 reduce rows g*4 .. g*4+3
        if ((warp >> 2) == (g & 3)) {
            const int row = g * 4 + (warp & 3);
            float p = (lane < 16) ? s_part[row][lane] : 0.0f;
#pragma unroll
            for (int off = 8; off >= 1; off >>= 1)
                p += __shfl_xor_sync(0xffffffffu, p, off);
            if (lane == 0)
                s_h[row] = __fdividef(0.5f, fmaf(0.5f, p, 1024.0f));
        }
        __syncthreads();

        // rotate carry (fully unrolled -> register renaming, no moves)
#pragma unroll
        for (int u = 0; u < 4; u++) carry[u] = fresh[u];
    }

    // tail: store the last group's rows
#pragma unroll
    for (int u = 0; u < 4; u++) {
        const int i = (NGRP - 1) * 4 + u;
        const float h = s_h[i];
        const float2 lo = __half22float2(u_to_h2(carry[u].x));
        const float2 hi = __half22float2(u_to_h2(carry[u].y));
        float4 o;
        o.x = fmaf(lo.x, h, h);
        o.y = fmaf(lo.y, h, h);
        o.z = fmaf(hi.x, h, h);
        o.w = fmaf(hi.y, h, h);
        __stcs(obase0 + (size_t)i * (LEN / 4), o);
    }
}

extern "C" void kernel_launch(void* const* d_in, const int* in_sizes, int n_in,
                              void* d_out, int out_size)
{
    const float* x        = (const float*)d_in[0];   // (8, 2048, 512)
    const float* rotation = (const float*)d_in[1];   // (512, 8)
    float* out = (float*)d_out;                      // (8, 2048, 2048)

    rot_kernel<<<512, 256>>>(x, rotation);

    dim3 grid(LEN / IT, BATCH);                      // (64, 8)
    attn_kernel<<<grid, THR>>>(out);
}